// round 14
// baseline (speedup 1.0000x reference)
#include <cuda_runtime.h>
#include <cuda_fp16.h>
#include <math.h>
#include <stdint.h>

#define NN 100000
#define EE 600000
#define HH 128
#define LL 3
#define BB 16
#define NF 12
#define EF 3
#define BN_EPS 1e-5f
#define LN_EPS 1e-5f

// fp16 fragment-major weight scratch offsets (uint32 words, each = half2)
#define W1OFF 0                 // 3 x 16384
#define W2OFF 49152             // 3 x 16384
#define O1OFF 98304             // 32768
#define O2OFF 131072            // 8192
#define WTOT  139264

// ---------------- scratch (static device globals; no runtime alloc) ----------
__device__ __align__(128) float    g_hcat[(size_t)NN * 4 * HH];
__device__ __align__(128) uint32_t g_aggh[(size_t)NN * 64];   // fp16x2 packed agg
__device__ __align__(128) uint32_t g_wtf [WTOT];              // fp16x2 packed weights
__device__ float g_gsum[BB * HH];
__device__ float g_cnt [BB];
__device__ int   g_deg [NN];
__device__ int   g_rows[NN];
__device__ int   g_fill[NN];
__device__ __align__(128) int   g_esrc[EE];
__device__ __align__(128) float g_sea [NN * 4];
__device__ int   g_bsum[128];
__device__ int   g_boff[128];

// ---------------- helpers ----------------------------------------------------
__device__ __forceinline__ uint32_t pkh2(float lo, float hi) {
    __half2 h = __floats2half2_rn(lo, hi);
    return *(uint32_t*)&h;
}
__device__ __forceinline__ void mma_f16(float* c, const uint32_t* a, const uint32_t* b) {
    asm volatile(
        "mma.sync.aligned.m16n8k16.row.col.f32.f16.f16.f32 "
        "{%0,%1,%2,%3},{%4,%5,%6,%7},{%8,%9},{%0,%1,%2,%3};\n"
        : "+f"(c[0]), "+f"(c[1]), "+f"(c[2]), "+f"(c[3])
        : "r"(a[0]), "r"(a[1]), "r"(a[2]), "r"(a[3]), "r"(b[0]), "r"(b[1]));
}
__device__ __forceinline__ uint32_t sptr(const void* p) {
    return (uint32_t)__cvta_generic_to_shared(p);
}
__device__ __forceinline__ void cp16(uint32_t d, const void* s, int sz) {
    asm volatile("cp.async.cg.shared.global [%0], [%1], 16, %2;\n"
                 :: "r"(d), "l"(s), "r"(sz));
}
__device__ __forceinline__ void cp_commit() {
    asm volatile("cp.async.commit_group;\n" ::: "memory");
}
template <int N> __device__ __forceinline__ void cp_wait() {
    asm volatile("cp.async.wait_group %0;\n" :: "n"(N) : "memory");
}

// ---------------- prep: zero counters + pack ALL weights to fp16 --------------
// word i = half2{W[k0][n], W[k0+1][n]}, i = ((c*NWG+nw)*32+lane)*16 + nt*2 + r,
// k0 = 16c + 2lc + 8r, n = 64nw + 8nt + lr
__global__ void k_prep(const float* __restrict__ w1, const float* __restrict__ w2,
                       const float* __restrict__ o1, const float* __restrict__ o2) {
    int i = blockIdx.x * blockDim.x + threadIdx.x;
    if (i < BB * HH) g_gsum[i] = 0.f;
    if (i < BB) g_cnt[i] = 0.f;
    if (i < NN) {
        g_deg[i] = 0;
        g_fill[i] = 0;
        *(float4*)(g_sea + i * 4) = make_float4(0.f, 0.f, 0.f, 0.f);
    }
    if (i >= WTOT) return;
    const float* src;
    int N, rel;
    if (i < W2OFF) {
        int l = i >> 14; rel = i & 16383;
        src = w1 + (size_t)l * 32768; N = 256;
    } else if (i < O1OFF) {
        int j = i - W2OFF;
        int l = j >> 14; rel = j & 16383;
        src = w2 + (size_t)l * 32768; N = 128;
    } else if (i < O2OFF) {
        rel = i - O1OFF; src = o1; N = 128;
    } else {
        rel = i - O2OFF; src = o2; N = 128;
    }
    int v = rel & 15, lane = (rel >> 4) & 31, r2 = rel >> 9;
    int NWG = N >> 6;
    int nw = r2 % NWG, c = r2 / NWG;
    int nt = v >> 1, r = v & 1;
    int lc = lane & 3, lr = lane >> 2;
    int k0 = c * 16 + 2 * lc + 8 * r;
    int n = nw * 64 + nt * 8 + lr;
    g_wtf[i] = pkh2(src[(size_t)k0 * N + n], src[(size_t)(k0 + 1) * N + n]);
}

__global__ void k_input(const float* __restrict__ x, const float* __restrict__ W,
                        const float* __restrict__ b) {
    int idx = blockIdx.x * blockDim.x + threadIdx.x;
    if (idx >= NN * HH) return;
    int n = idx >> 7, j = idx & 127;
    const float* xr = x + (size_t)n * NF;
    float acc = b[j];
#pragma unroll
    for (int f = 0; f < NF; f++) acc += xr[f] * W[f * HH + j];
    g_hcat[(size_t)n * 512 + j] = acc;
}

// ---------------- CSR build ----------------------------------------------------
__global__ void k_count(const int* __restrict__ ei) {
    int e = blockIdx.x * blockDim.x + threadIdx.x;
    if (e < EE) atomicAdd(&g_deg[ei[EE + e]], 1);
}
__global__ void k_scan1() {
    __shared__ int ss[256];
    int t = threadIdx.x;
    int base = blockIdx.x * 1024;
    int v[4], s = 0;
#pragma unroll
    for (int j = 0; j < 4; j++) {
        int i = base + t * 4 + j;
        v[j] = (i < NN) ? g_deg[i] : 0;
        s += v[j];
    }
    ss[t] = s;
    __syncthreads();
#pragma unroll
    for (int off = 1; off < 256; off <<= 1) {
        int a = (t >= off) ? ss[t - off] : 0;
        __syncthreads();
        ss[t] += a;
        __syncthreads();
    }
    if (t == 255) g_bsum[blockIdx.x] = ss[255];
    int run = ss[t] - s;
#pragma unroll
    for (int j = 0; j < 4; j++) {
        int i = base + t * 4 + j;
        if (i < NN) g_rows[i] = run;
        run += v[j];
    }
}
__global__ void k_scan2(int nb) {
    __shared__ int ss[128];
    int t = threadIdx.x;
    int v = (t < nb) ? g_bsum[t] : 0;
    ss[t] = v;
    __syncthreads();
#pragma unroll
    for (int off = 1; off < 128; off <<= 1) {
        int a = (t >= off) ? ss[t - off] : 0;
        __syncthreads();
        ss[t] += a;
        __syncthreads();
    }
    if (t < nb) g_boff[t] = ss[t] - v;
}
__global__ void k_place(const int* __restrict__ ei, const float* __restrict__ ea) {
    int e = blockIdx.x * blockDim.x + threadIdx.x;
    if (e >= EE) return;
    int d = ei[EE + e];
    int p = g_rows[d] + g_boff[d >> 10] + atomicAdd(&g_fill[d], 1);
    g_esrc[p] = ei[e];
    atomicAdd(&g_sea[d * 4 + 0], ea[e * 3 + 0]);
    atomicAdd(&g_sea[d * 4 + 1], ea[e * 3 + 1]);
    atomicAdd(&g_sea[d * 4 + 2], ea[e * 3 + 2]);
}

// ---------------- per-node gather: adds only; fp16-packed output --------------
__global__ void k_gather(const float* __restrict__ eW, const float* __restrict__ eb,
                         const float* __restrict__ eps, int layer) {
    int warp = (blockIdx.x * blockDim.x + threadIdx.x) >> 5;
    int lane = threadIdx.x & 31;
    if (warp >= NN) return;
    int j = lane * 4;
    const float* W = eW + layer * EF * HH;
    float4 w0 = *(const float4*)(W + 0 * HH + j);
    float4 w1 = *(const float4*)(W + 1 * HH + j);
    float4 w2 = *(const float4*)(W + 2 * HH + j);
    float4 bv = *(const float4*)(eb + layer * HH + j);
    const float* hl = g_hcat + (size_t)layer * HH;
    float4 hd = *(const float4*)(hl + (size_t)warp * 512 + j);
    float4 S  = *(const float4*)(g_sea + warp * 4);
    int start = g_rows[warp] + g_boff[warp >> 10];
    int deg = g_deg[warp];
    const int* es = g_esrc + start;

    float e1 = 1.f + eps[layer];
    float dg = (float)deg;
    float ax = e1 * hd.x + dg * bv.x + S.x * w0.x + S.y * w1.x + S.z * w2.x;
    float ay = e1 * hd.y + dg * bv.y + S.x * w0.y + S.y * w1.y + S.z * w2.y;
    float az = e1 * hd.z + dg * bv.z + S.x * w0.z + S.y * w1.z + S.z * w2.z;
    float aw = e1 * hd.w + dg * bv.w + S.x * w0.w + S.y * w1.w + S.z * w2.w;
    float bx = 0.f, by = 0.f, bz = 0.f, bw = 0.f;

    int k = 0;
    for (; k + 4 <= deg; k += 4) {
        int s0 = es[k], s1 = es[k + 1], s2 = es[k + 2], s3 = es[k + 3];
        float4 h0 = *(const float4*)(hl + (size_t)s0 * 512 + j);
        float4 h1 = *(const float4*)(hl + (size_t)s1 * 512 + j);
        float4 h2 = *(const float4*)(hl + (size_t)s2 * 512 + j);
        float4 h3 = *(const float4*)(hl + (size_t)s3 * 512 + j);
        ax += h0.x; ay += h0.y; az += h0.z; aw += h0.w;
        bx += h1.x; by += h1.y; bz += h1.z; bw += h1.w;
        ax += h2.x; ay += h2.y; az += h2.z; aw += h2.w;
        bx += h3.x; by += h3.y; bz += h3.z; bw += h3.w;
    }
    for (; k < deg; k++) {
        int s0 = es[k];
        float4 h0 = *(const float4*)(hl + (size_t)s0 * 512 + j);
        ax += h0.x; ay += h0.y; az += h0.z; aw += h0.w;
    }
    uint2 o;
    o.x = pkh2(ax + bx, ay + by);
    o.y = pkh2(az + bz, aw + bw);
    *(uint2*)(g_aggh + (size_t)warp * 64 + lane * 2) = o;
}

// ---------------- fused GIN MLP: fp16 m16n8k16, BM=64, 256 thr, 2 CTA/SM ------
__global__ void __launch_bounds__(256, 2)
k_mlp(const uint32_t* __restrict__ Aagg, const uint32_t* __restrict__ W1p,
      const uint32_t* __restrict__ W2p,
      const float* __restrict__ b1v, const float* __restrict__ g1,
      const float* __restrict__ bt1, const float* __restrict__ rm1,
      const float* __restrict__ rv1,
      const float* __restrict__ b2v, const float* __restrict__ g2,
      const float* __restrict__ bt2, const float* __restrict__ rm2,
      const float* __restrict__ rv2,
      const float* __restrict__ hres,
      const float* __restrict__ lng, const float* __restrict__ lnb,
      float* __restrict__ out) {
    constexpr int BM = 64;
    constexpr int NWG1 = 4, CH1 = 8;       // phase 1: K=128, chunks of 16
    constexpr int NWG2 = 2, CH2 = 16;      // phase 2: K=256
    constexpr int ABYTES = BM * 48;        // rows of 8 words, stride 12
    constexpr int B1BYTES = NWG1 * 32 * 80;// 10240
    constexpr int STG1 = ABYTES + B1BYTES; // 13312 (x3 = 39936)
    constexpr int B2BYTES = NWG2 * 32 * 80;// 5120
    constexpr int ZS = 132;                // z word stride
    constexpr int W2RING = BM * ZS * 4;    // 33792

    extern __shared__ char dsm[];
    __shared__ float red[BM * 4];
    uint32_t sb = sptr(dsm);

    int t = threadIdx.x;
    int lane = t & 31, wid = t >> 5;
    int lr = lane >> 2, lc = lane & 3;
    int n0 = blockIdx.x * BM;

    int mw = wid >> 2, nw = wid & 3;       // phase 1: 2M x 4N
    int wrow = mw * 32, wcol = nw * 64;

    float acc[2][8][4];
#pragma unroll
    for (int mt = 0; mt < 2; mt++)
#pragma unroll
        for (int nt = 0; nt < 8; nt++)
#pragma unroll
            for (int i = 0; i < 4; i++) acc[mt][nt][i] = 0.f;

    auto load_t1 = [&](int c, int st) {
        uint32_t ab = sb + st * STG1;
        uint32_t bb = ab + ABYTES;
        if (t < 128) {                      // A: 64 rows x 32B
            int r = t >> 1, c4 = t & 1;
            int n = n0 + r;
            const uint32_t* src = Aagg + (size_t)(n < NN ? n : 0) * 64 + c * 8 + c4 * 4;
            cp16(ab + r * 48 + c4 * 16, src, n < NN ? 16 : 0);
        }
#pragma unroll
        for (int i = 0; i < 2; i++) {       // B1: 2048 words
            int f = t + i * 256;
            cp16(bb + (f >> 2) * 80 + (f & 3) * 16, W1p + (size_t)c * 2048 + f * 4, 16);
        }
    };
    auto load_w2 = [&](int c2, int jb) {
        uint32_t bb = sb + W2RING + jb * B2BYTES;
        cp16(bb + (t >> 2) * 80 + (t & 3) * 16, W2p + (size_t)c2 * 1024 + t * 4, 16);
    };

    load_t1(0, 0);
    cp_commit();
    load_t1(1, 1);
    cp_commit();
    for (int c = 0; c < CH1; c++) {
        int st = c % 3;
        if (c + 1 < CH1) cp_wait<1>(); else cp_wait<0>();
        __syncthreads();
        if (c + 2 < CH1) {
            load_t1(c + 2, (c + 2) % 3);
            cp_commit();
        }
        const uint32_t* As = (const uint32_t*)(dsm + st * STG1);
        const char*    Bb = dsm + st * STG1 + ABYTES;
        uint32_t a[2][4];
#pragma unroll
        for (int mt = 0; mt < 2; mt++) {
            int base = (wrow + mt * 16 + lr) * 12 + lc;
            a[mt][0] = As[base];
            a[mt][1] = As[base + 96];
            a[mt][2] = As[base + 4];
            a[mt][3] = As[base + 100];
        }
        const float4* bf = (const float4*)(Bb + (size_t)(nw * 32 + lane) * 80);
        uint32_t b[8][2];
#pragma unroll
        for (int g = 0; g < 4; g++) {
            float4 f4 = bf[g];
            b[2 * g + 0][0] = __float_as_uint(f4.x);
            b[2 * g + 0][1] = __float_as_uint(f4.y);
            b[2 * g + 1][0] = __float_as_uint(f4.z);
            b[2 * g + 1][1] = __float_as_uint(f4.w);
        }
#pragma unroll
        for (int mt = 0; mt < 2; mt++)
#pragma unroll
            for (int nt = 0; nt < 8; nt++)
                mma_f16(acc[mt][nt], a[mt], b[nt]);
    }
    __syncthreads();

    load_w2(0, 0);
    cp_commit();
    load_w2(1, 1);
    cp_commit();

    // ---- z = fp16(relu(bn1(acc + b1))) -> smem stash (packed half2) ----
    uint32_t* Zw = (uint32_t*)dsm;
    {
        float bsv[8][2], sc[8][2], sh[8][2];
#pragma unroll
        for (int nt = 0; nt < 8; nt++)
#pragma unroll
            for (int q = 0; q < 2; q++) {
                int col = wcol + nt * 8 + lc * 2 + q;
                bsv[nt][q] = b1v[col];
                float s = g1[col] * rsqrtf(rv1[col] + BN_EPS);
                sc[nt][q] = s;
                sh[nt][q] = bt1[col] - rm1[col] * s;
            }
#pragma unroll
        for (int mt = 0; mt < 2; mt++)
#pragma unroll
            for (int half = 0; half < 2; half++) {
                int row = wrow + mt * 16 + lr + half * 8;
#pragma unroll
                for (int nt = 0; nt < 8; nt++) {
                    float v0 = acc[mt][nt][half * 2 + 0] + bsv[nt][0];
                    v0 = fmaxf(v0 * sc[nt][0] + sh[nt][0], 0.f);
                    float v1 = acc[mt][nt][half * 2 + 1] + bsv[nt][1];
                    v1 = fmaxf(v1 * sc[nt][1] + sh[nt][1], 0.f);
                    Zw[row * ZS + wcol / 2 + nt * 4 + lc] = pkh2(v0, v1);
                }
            }
    }
    __syncthreads();

    // ---- phase 2: z @ W2, warp tile 16x64, 8M x 2N ----
    int mw2 = wid >> 1, nw2 = wid & 1;
    int wrow2 = mw2 * 16, wcol2 = nw2 * 64;
    float acc2[8][4];
#pragma unroll
    for (int nt = 0; nt < 8; nt++)
#pragma unroll
        for (int i = 0; i < 4; i++) acc2[nt][i] = 0.f;

    for (int c2 = 0; c2 < CH2; c2++) {
        int jb = c2 % 3;
        if (c2 + 1 < CH2) cp_wait<1>(); else cp_wait<0>();
        __syncthreads();
        if (c2 + 2 < CH2) {
            load_w2(c2 + 2, (c2 + 2) % 3);
            cp_commit();
        }
        const char* Bb = dsm + W2RING + jb * B2BYTES;
        uint32_t a[4];
        {
            int base = (wrow2 + lr) * ZS + c2 * 8 + lc;
            a[0] = Zw[base];
            a[1] = Zw[base + 8 * ZS];
            a[2] = Zw[base + 4];
            a[3] = Zw[base + 8 * ZS + 4];
        }
        const float4* bf = (const float4*)(Bb + (size_t)(nw2 * 32 + lane) * 80);
        uint32_t b[8][2];
#pragma unroll
        for (int g = 0; g < 4; g++) {
            float4 f4 = bf[g];
            b[2 * g + 0][0] = __float_as_uint(f4.x);
            b[2 * g + 0][1] = __float_as_uint(f4.y);
            b[2 * g + 1][0] = __float_as_uint(f4.z);
            b[2 * g + 1][1] = __float_as_uint(f4.w);
        }
#pragma unroll
        for (int nt = 0; nt < 8; nt++)
            mma_f16(acc2[nt], a, b[nt]);
    }

    // ---- epilogue: bn2+relu + residual, LN, write hcat slot (stride 512) ----
    float bsv2[8][2], sc2[8][2], sh2[8][2];
#pragma unroll
    for (int nt = 0; nt < 8; nt++)
#pragma unroll
        for (int q = 0; q < 2; q++) {
            int col = wcol2 + nt * 8 + lc * 2 + q;
            bsv2[nt][q] = b2v[col];
            float s = g2[col] * rsqrtf(rv2[col] + BN_EPS);
            sc2[nt][q] = s;
            sh2[nt][q] = bt2[col] - rm2[col] * s;
        }
#pragma unroll
    for (int half = 0; half < 2; half++) {
        int row = wrow2 + lr + half * 8;
        int n = n0 + row;
        float s = 0.f, sq = 0.f;
#pragma unroll
        for (int nt = 0; nt < 8; nt++)
#pragma unroll
            for (int q = 0; q < 2; q++) {
                int col = wcol2 + nt * 8 + lc * 2 + q;
                float v = acc2[nt][half * 2 + q] + bsv2[nt][q];
                v = fmaxf(v * sc2[nt][q] + sh2[nt][q], 0.f);
                if (n < NN) v += hres[(size_t)n * 512 + col];
                acc2[nt][half * 2 + q] = v;
                s += v;
                sq += v * v;
            }
        s  += __shfl_xor_sync(0xffffffffu, s, 1);
        sq += __shfl_xor_sync(0xffffffffu, sq, 1);
        s  += __shfl_xor_sync(0xffffffffu, s, 2);
        sq += __shfl_xor_sync(0xffffffffu, sq, 2);
        if (lc == 0) {
            red[(row * 2 + nw2) * 2 + 0] = s;
            red[(row * 2 + nw2) * 2 + 1] = sq;
        }
    }
    __syncthreads();
#pragma unroll
    for (int half = 0; half < 2; half++) {
        int row = wrow2 + lr + half * 8;
        int n = n0 + row;
        if (n >= NN) continue;
        float s  = red[(row * 2 + 0) * 2 + 0] + red[(row * 2 + 1) * 2 + 0];
        float sq = red[(row * 2 + 0) * 2 + 1] + red[(row * 2 + 1) * 2 + 1];
        float mu = s * (1.f / 128.f);
        float var = sq * (1.f / 128.f) - mu * mu;
        float inv = rsqrtf(var + LN_EPS);
#pragma unroll
        for (int nt = 0; nt < 8; nt++)
#pragma unroll
            for (int q = 0; q < 2; q++) {
                int col = wcol2 + nt * 8 + lc * 2 + q;
                float v = acc2[nt][half * 2 + q];
                out[(size_t)n * 512 + col] = (v - mu) * inv * lng[col] + lnb[col];
            }
    }
}

// ---------------- fused output head: fp16, BM=128, 256 thr --------------------
__global__ void __launch_bounds__(256, 2)
k_gemm_out(const float* __restrict__ A, const uint32_t* __restrict__ W1p,
           const uint32_t* __restrict__ W2p,
           const float* __restrict__ b1, const float* __restrict__ b2,
           float* __restrict__ out) {
    constexpr int NWG = 2, BM = 128, K = 512;
    constexpr int CH = K / 16;              // 32
    constexpr int ABYTES = BM * 80;         // fp32 rows of 16, stride 20
    constexpr int BBYTES = NWG * 32 * 80;   // 5120
    constexpr int STG = ABYTES + BBYTES;    // 15360 (x3 = 46080)
    constexpr int ZS = 68;                  // z word stride (64 + 4 pad)
    constexpr int B2OFF = BM * ZS * 4;      // 34816

    extern __shared__ char dsm[];
    uint32_t sb = sptr(dsm);

    int t = threadIdx.x;
    int lane = t & 31, wid = t >> 5;
    int mw = wid >> 1, nw = wid & 1;        // 4M x 2N, warp tile 32x64
    int wrow = mw * 32, wcol = nw * 64;
    int lr = lane >> 2, lc = lane & 3;
    int n0 = blockIdx.x * BM;

    float acc[2][8][4];
#pragma unroll
    for (int mt = 0; mt < 2; mt++)
#pragma unroll
        for (int nt = 0; nt < 8; nt++)
#pragma unroll
            for (int i = 0; i < 4; i++) acc[mt][nt][i] = 0.f;

    auto load_tiles = [&](int c, int st) {
        uint32_t ab = sb + st * STG;
        uint32_t bb = ab + ABYTES;
#pragma unroll
        for (int i = 0; i < 2; i++) {        // A: 512 x 16B
            int f = t + i * 256;
            int r = f >> 2, c4 = f & 3;
            int n = n0 + r;
            const float* src = A + (size_t)(n < NN ? n : 0) * K + c * 16 + c4 * 4;
            cp16(ab + r * 80 + c4 * 16, src, n < NN ? 16 : 0);
        }
        cp16(bb + (t >> 2) * 80 + (t & 3) * 16, W1p + (size_t)c * 1024 + t * 4, 16);
    };
    auto load_w2 = [&](int c2, int jbuf) {
        uint32_t bb = sb + B2OFF + jbuf * BBYTES;
        cp16(bb + (t >> 2) * 80 + (t & 3) * 16, W2p + (size_t)c2 * 1024 + t * 4, 16);
    };

    load_tiles(0, 0);
    cp_commit();
    load_tiles(1, 1);
    cp_commit();
    for (int c = 0; c < CH; c++) {
        int st = c % 3;
        if (c + 1 < CH) cp_wait<1>(); else cp_wait<0>();
        __syncthreads();
        if (c + 2 < CH) {
            load_tiles(c + 2, (c + 2) % 3);
            cp_commit();
        }
        const float* As = (const float*)(dsm + st * STG);
        const char*  Bb = dsm + st * STG + ABYTES;
        uint32_t a[2][4];
#pragma unroll
        for (int mt = 0; mt < 2; mt++) {
            int base = (wrow + mt * 16 + lr) * 20;
            float2 f0 = *(const float2*)(As + base + 2 * lc);
            float2 f1 = *(const float2*)(As + base + 160 + 2 * lc);
            float2 f2 = *(const float2*)(As + base + 2 * lc + 8);
            float2 f3 = *(const float2*)(As + base + 160 + 2 * lc + 8);
            a[mt][0] = pkh2(f0.x, f0.y);
            a[mt][1] = pkh2(f1.x, f1.y);
            a[mt][2] = pkh2(f2.x, f2.y);
            a[mt][3] = pkh2(f3.x, f3.y);
        }
        const float4* bf = (const float4*)(Bb + (size_t)(nw * 32 + lane) * 80);
        uint32_t b[8][2];
#pragma unroll
        for (int g = 0; g < 4; g++) {
            float4 f4 = bf[g];
            b[2 * g + 0][0] = __float_as_uint(f4.x);
            b[2 * g + 0][1] = __float_as_uint(f4.y);
            b[2 * g + 1][0] = __float_as_uint(f4.z);
            b[2 * g + 1][1] = __float_as_uint(f4.w);
        }
#pragma unroll
        for (int mt = 0; mt < 2; mt++)
#pragma unroll
            for (int nt = 0; nt < 8; nt++)
                mma_f16(acc[mt][nt], a[mt], b[nt]);
    }
    __syncthreads();

    load_w2(0, 0);
    cp_commit();
    load_w2(1, 1);
    cp_commit();

    // z = fp16(relu(acc + b1)) -> smem (packed half2, stride 68 words)
    uint32_t* Zw = (uint32_t*)dsm;
    {
        float bsv[8][2];
#pragma unroll
        for (int nt = 0; nt < 8; nt++)
#pragma unroll
            for (int q = 0; q < 2; q++)
                bsv[nt][q] = b1[wcol + nt * 8 + lc * 2 + q];
#pragma unroll
        for (int mt = 0; mt < 2; mt++)
#pragma unroll
            for (int half = 0; half < 2; half++) {
                int row = wrow + mt * 16 + lr + half * 8;
#pragma unroll
                for (int nt = 0; nt < 8; nt++) {
                    float v0 = fmaxf(acc[mt][nt][half * 2 + 0] + bsv[nt][0], 0.f);
                    float v1 = fmaxf(acc[mt][nt][half * 2 + 1] + bsv[nt][1], 0.f);
                    Zw[row * ZS + wcol / 2 + nt * 4 + lc] = pkh2(v0, v1);
                }
            }
    }
    __syncthreads();

#pragma unroll
    for (int mt = 0; mt < 2; mt++)
#pragma unroll
        for (int nt = 0; nt < 8; nt++)
#pragma unroll
            for (int i = 0; i < 4; i++) acc[mt][nt][i] = 0.f;

    for (int c2 = 0; c2 < 8; c2++) {
        int jb = c2 % 3;
        if (c2 + 1 < 8) cp_wait<1>(); else cp_wait<0>();
        __syncthreads();
        if (c2 + 2 < 8) {
            load_w2(c2 + 2, (c2 + 2) % 3);
            cp_commit();
        }
        const char* Bb = dsm + B2OFF + jb * BBYTES;
        uint32_t a[2][4];
#pragma unroll
        for (int mt = 0; mt < 2; mt++) {
            int base = (wrow + mt * 16 + lr) * ZS + c2 * 8 + lc;
            a[mt][0] = Zw[base];
            a[mt][1] = Zw[base + 8 * ZS];
            a[mt][2] = Zw[base + 4];
            a[mt][3] = Zw[base + 8 * ZS + 4];
        }
        const float4* bf = (const float4*)(Bb + (size_t)(nw * 32 + lane) * 80);
        uint32_t b[8][2];
#pragma unroll
        for (int g = 0; g < 4; g++) {
            float4 f4 = bf[g];
            b[2 * g + 0][0] = __float_as_uint(f4.x);
            b[2 * g + 0][1] = __float_as_uint(f4.y);
            b[2 * g + 1][0] = __float_as_uint(f4.z);
            b[2 * g + 1][1] = __float_as_uint(f4.w);
        }
#pragma unroll
        for (int mt = 0; mt < 2; mt++)
#pragma unroll
            for (int nt = 0; nt < 8; nt++)
                mma_f16(acc[mt][nt], a[mt], b[nt]);
    }

    float bsv2[8][2];
#pragma unroll
    for (int nt = 0; nt < 8; nt++)
#pragma unroll
        for (int q = 0; q < 2; q++)
            bsv2[nt][q] = b2[wcol + nt * 8 + lc * 2 + q];
#pragma unroll
    for (int mt = 0; mt < 2; mt++)
#pragma unroll
        for (int half = 0; half < 2; half++) {
            int row = wrow + mt * 16 + lr + half * 8;
            int n = n0 + row;
            if (n >= NN) continue;
#pragma unroll
            for (int nt = 0; nt < 8; nt++)
#pragma unroll
                for (int q = 0; q < 2; q++) {
                    int col = wcol + nt * 8 + lc * 2 + q;
                    out[(size_t)n * 128 + col] =
                        acc[mt][nt][half * 2 + q] + bsv2[nt][q];
                }
        }
}

// ---------------- pool ---------------------------------------------------------
__global__ void k_pool(const int* __restrict__ batch, const float* __restrict__ emb) {
    int c = blockIdx.x;
    int j = threadIdx.x;
    int n0 = c * 32;
    __shared__ int sb[32];
    if (j < 32) sb[j] = (n0 + j < NN) ? batch[n0 + j] : -1;
    __syncthreads();
    float acc = 0.f;
    int bcur = sb[0];
    for (int m = 0; m < 32; m++) {
        int b = sb[m];
        if (b < 0) break;
        if (b != bcur) {
            atomicAdd(&g_gsum[bcur * HH + j], acc);
            acc = 0.f;
            bcur = b;
        }
        acc += emb[(size_t)(n0 + m) * HH + j];
    }
    if (bcur >= 0) atomicAdd(&g_gsum[bcur * HH + j], acc);
    if (j == 0) {
        float cn = 0.f;
        int bc = sb[0];
        for (int m = 0; m < 32; m++) {
            int b = sb[m];
            if (b < 0) break;
            if (b != bc) { atomicAdd(&g_cnt[bc], cn); cn = 0.f; bc = b; }
            cn += 1.f;
        }
        if (bc >= 0) atomicAdd(&g_cnt[bc], cn);
    }
}

__global__ void k_finish(float* __restrict__ out_graph) {
    int i = blockIdx.x * blockDim.x + threadIdx.x;
    if (i >= BB * HH) return;
    out_graph[i] = g_gsum[i] / fmaxf(g_cnt[i >> 7], 1.f);
}

// ---------------- launcher ------------------------------------------------------
extern "C" void kernel_launch(void* const* d_in, const int* in_sizes, int n_in,
                              void* d_out, int out_size) {
    const float* x      = (const float*)d_in[0];
    const int*   ei     = (const int*)  d_in[1];
    const float* ea     = (const float*)d_in[2];
    const int*   batch  = (const int*)  d_in[3];
    const float* in_W   = (const float*)d_in[4];
    const float* in_b   = (const float*)d_in[5];
    const float* edge_W = (const float*)d_in[6];
    const float* edge_b = (const float*)d_in[7];
    const float* mlp_W1 = (const float*)d_in[8];
    const float* mlp_b1 = (const float*)d_in[9];
    const float* bn1_g  = (const float*)d_in[10];
    const float* bn1_b  = (const float*)d_in[11];
    const float* bn1_rm = (const float*)d_in[12];
    const float* bn1_rv = (const float*)d_in[13];
    const float* mlp_W2 = (const float*)d_in[14];
    const float* mlp_b2 = (const float*)d_in[15];
    const float* bn2_g  = (const float*)d_in[16];
    const float* bn2_b  = (const float*)d_in[17];
    const float* bn2_rm = (const float*)d_in[18];
    const float* bn2_rv = (const float*)d_in[19];
    const float* eps    = (const float*)d_in[20];
    const float* ln_g   = (const float*)d_in[21];
    const float* ln_b   = (const float*)d_in[22];
    const float* out_W1 = (const float*)d_in[23];
    const float* out_b1 = (const float*)d_in[24];
    const float* out_W2 = (const float*)d_in[25];
    const float* out_b2 = (const float*)d_in[26];

    float* node_emb  = (float*)d_out;
    float* graph_emb = (float*)d_out + (size_t)NN * HH;

    float* g_hcat_p;    cudaGetSymbolAddress((void**)&g_hcat_p, g_hcat);
    uint32_t* g_aggh_p; cudaGetSymbolAddress((void**)&g_aggh_p, g_aggh);
    uint32_t* g_wtf_p;  cudaGetSymbolAddress((void**)&g_wtf_p,  g_wtf);

    const int SMMLP = 33792 + 3 * 5120;   // 49152 (covers 39936 phase-1 ring)
    const int SMOUT = 34816 + 3 * 5120;   // 50176 (covers 46080 phase-1 ring)
    cudaFuncSetAttribute(k_mlp,
                         cudaFuncAttributeMaxDynamicSharedMemorySize, SMMLP);
    cudaFuncSetAttribute(k_gemm_out,
                         cudaFuncAttributeMaxDynamicSharedMemorySize, SMOUT);

    const int NT = 256;
    k_prep<<<(WTOT + NT - 1) / NT, NT>>>(mlp_W1, mlp_W2, out_W1, out_W2);
    k_input<<<(NN * HH + NT - 1) / NT, NT>>>(x, in_W, in_b);

    // CSR build
    k_count<<<(EE + NT - 1) / NT, NT>>>(ei);
    k_scan1<<<(NN + 1023) / 1024, 256>>>();
    k_scan2<<<1, 128>>>((NN + 1023) / 1024);
    k_place<<<(EE + NT - 1) / NT, NT>>>(ei, ea);

    const int grid64  = (NN + 63) / 64;
    const int grid128 = (NN + 127) / 128;
    for (int l = 0; l < LL; l++) {
        k_gather<<<(NN * 32 + NT - 1) / NT, NT>>>(edge_W, edge_b, eps, l);
        k_mlp<<<grid64, 256, SMMLP>>>(
            g_aggh_p,
            g_wtf_p + W1OFF + (size_t)l * 16384,
            g_wtf_p + W2OFF + (size_t)l * 16384,
            mlp_b1 + l * 256, bn1_g + l * 256, bn1_b + l * 256,
            bn1_rm + l * 256, bn1_rv + l * 256,
            mlp_b2 + l * 128, bn2_g + l * 128, bn2_b + l * 128,
            bn2_rm + l * 128, bn2_rv + l * 128,
            g_hcat_p + l * HH, ln_g + l * 128, ln_b + l * 128,
            g_hcat_p + (l + 1) * HH);
    }
    k_gemm_out<<<grid128, 256, SMOUT>>>(
        g_hcat_p, g_wtf_p + O1OFF, g_wtf_p + O2OFF, out_b1, out_b2, node_emb);

    k_pool<<<(NN + 31) / 32, 128>>>(batch, node_emb);
    k_finish<<<(BB * HH + NT - 1) / NT, NT>>>(graph_emb);
}

// round 15
// speedup vs baseline: 1.0378x; 1.0378x over previous
#include <cuda_runtime.h>
#include <cuda_fp16.h>
#include <math.h>
#include <stdint.h>

#define NN 100000
#define EE 600000
#define HH 128
#define LL 3
#define BB 16
#define NF 12
#define EF 3
#define BN_EPS 1e-5f
#define LN_EPS 1e-5f

// fp16 fragment-major weight scratch offsets (uint32 words, each = half2)
#define W1OFF 0                 // 3 x 16384
#define W2OFF 49152             // 3 x 16384
#define O1OFF 98304             // 32768
#define O2OFF 131072            // 8192
#define WTOT  139264

// ---------------- scratch (static device globals; no runtime alloc) ----------
__device__ __align__(128) float    g_hcat [(size_t)NN * 4 * HH];
__device__ __align__(128) uint32_t g_hcath[(size_t)NN * 256];  // fp16x2 copy of hcat
__device__ __align__(128) uint32_t g_aggh [(size_t)NN * 64];   // fp16x2 packed agg
__device__ __align__(128) uint32_t g_wtf  [WTOT];
__device__ float g_gsum[BB * HH];
__device__ float g_cnt [BB];
__device__ int   g_deg [NN];
__device__ int   g_rows[NN];
__device__ int   g_fill[NN];
__device__ __align__(128) int   g_esrc[EE];
__device__ __align__(128) float g_sea [NN * 4];
__device__ int   g_bsum[128];
__device__ int   g_boff[128];

// ---------------- helpers ----------------------------------------------------
__device__ __forceinline__ uint32_t pkh2(float lo, float hi) {
    __half2 h = __floats2half2_rn(lo, hi);
    return *(uint32_t*)&h;
}
__device__ __forceinline__ void mma_f16(float* c, const uint32_t* a, const uint32_t* b) {
    asm volatile(
        "mma.sync.aligned.m16n8k16.row.col.f32.f16.f16.f32 "
        "{%0,%1,%2,%3},{%4,%5,%6,%7},{%8,%9},{%0,%1,%2,%3};\n"
        : "+f"(c[0]), "+f"(c[1]), "+f"(c[2]), "+f"(c[3])
        : "r"(a[0]), "r"(a[1]), "r"(a[2]), "r"(a[3]), "r"(b[0]), "r"(b[1]));
}
__device__ __forceinline__ uint32_t sptr(const void* p) {
    return (uint32_t)__cvta_generic_to_shared(p);
}
__device__ __forceinline__ void cp16(uint32_t d, const void* s, int sz) {
    asm volatile("cp.async.cg.shared.global [%0], [%1], 16, %2;\n"
                 :: "r"(d), "l"(s), "r"(sz));
}
__device__ __forceinline__ void cp_commit() {
    asm volatile("cp.async.commit_group;\n" ::: "memory");
}
template <int N> __device__ __forceinline__ void cp_wait() {
    asm volatile("cp.async.wait_group %0;\n" :: "n"(N) : "memory");
}

// ---------------- prep: zero counters + pack ALL weights to fp16 --------------
__global__ void k_prep(const float* __restrict__ w1, const float* __restrict__ w2,
                       const float* __restrict__ o1, const float* __restrict__ o2) {
    int i = blockIdx.x * blockDim.x + threadIdx.x;
    if (i < BB * HH) g_gsum[i] = 0.f;
    if (i < BB) g_cnt[i] = 0.f;
    if (i < NN) {
        g_deg[i] = 0;
        g_fill[i] = 0;
        *(float4*)(g_sea + i * 4) = make_float4(0.f, 0.f, 0.f, 0.f);
    }
    if (i >= WTOT) return;
    const float* src;
    int N, rel;
    if (i < W2OFF) {
        int l = i >> 14; rel = i & 16383;
        src = w1 + (size_t)l * 32768; N = 256;
    } else if (i < O1OFF) {
        int j = i - W2OFF;
        int l = j >> 14; rel = j & 16383;
        src = w2 + (size_t)l * 32768; N = 128;
    } else if (i < O2OFF) {
        rel = i - O1OFF; src = o1; N = 128;
    } else {
        rel = i - O2OFF; src = o2; N = 128;
    }
    int v = rel & 15, lane = (rel >> 4) & 31, r2 = rel >> 9;
    int NWG = N >> 6;
    int nw = r2 % NWG, c = r2 / NWG;
    int nt = v >> 1, r = v & 1;
    int lc = lane & 3, lr = lane >> 2;
    int k0 = c * 16 + 2 * lc + 8 * r;
    int n = nw * 64 + nt * 8 + lr;
    g_wtf[i] = pkh2(src[(size_t)k0 * N + n], src[(size_t)(k0 + 1) * N + n]);
}

// input proj: one thread per feature pair; writes fp32 hcat + fp16 copy
__global__ void k_input(const float* __restrict__ x, const float* __restrict__ W,
                        const float* __restrict__ b) {
    int idx = blockIdx.x * blockDim.x + threadIdx.x;
    if (idx >= NN * 64) return;
    int n = idx >> 6, jp = idx & 63;
    int j = jp * 2;
    const float* xr = x + (size_t)n * NF;
    float a0 = b[j], a1 = b[j + 1];
#pragma unroll
    for (int f = 0; f < NF; f++) {
        float xv = xr[f];
        a0 += xv * W[f * HH + j];
        a1 += xv * W[f * HH + j + 1];
    }
    *(float2*)(g_hcat + (size_t)n * 512 + j) = make_float2(a0, a1);
    g_hcath[(size_t)n * 256 + jp] = pkh2(a0, a1);
}

// ---------------- CSR build ----------------------------------------------------
__global__ void k_count(const int* __restrict__ ei) {
    int e = blockIdx.x * blockDim.x + threadIdx.x;
    if (e < EE) atomicAdd(&g_deg[ei[EE + e]], 1);
}
__global__ void k_scan1() {
    __shared__ int ss[256];
    int t = threadIdx.x;
    int base = blockIdx.x * 1024;
    int v[4], s = 0;
#pragma unroll
    for (int j = 0; j < 4; j++) {
        int i = base + t * 4 + j;
        v[j] = (i < NN) ? g_deg[i] : 0;
        s += v[j];
    }
    ss[t] = s;
    __syncthreads();
#pragma unroll
    for (int off = 1; off < 256; off <<= 1) {
        int a = (t >= off) ? ss[t - off] : 0;
        __syncthreads();
        ss[t] += a;
        __syncthreads();
    }
    if (t == 255) g_bsum[blockIdx.x] = ss[255];
    int run = ss[t] - s;
#pragma unroll
    for (int j = 0; j < 4; j++) {
        int i = base + t * 4 + j;
        if (i < NN) g_rows[i] = run;
        run += v[j];
    }
}
__global__ void k_scan2(int nb) {
    __shared__ int ss[128];
    int t = threadIdx.x;
    int v = (t < nb) ? g_bsum[t] : 0;
    ss[t] = v;
    __syncthreads();
#pragma unroll
    for (int off = 1; off < 128; off <<= 1) {
        int a = (t >= off) ? ss[t - off] : 0;
        __syncthreads();
        ss[t] += a;
        __syncthreads();
    }
    if (t < nb) g_boff[t] = ss[t] - v;
}
__global__ void k_place(const int* __restrict__ ei, const float* __restrict__ ea) {
    int e = blockIdx.x * blockDim.x + threadIdx.x;
    if (e >= EE) return;
    int d = ei[EE + e];
    int p = g_rows[d] + g_boff[d >> 10] + atomicAdd(&g_fill[d], 1);
    g_esrc[p] = ei[e];
    atomicAdd(&g_sea[d * 4 + 0], ea[e * 3 + 0]);
    atomicAdd(&g_sea[d * 4 + 1], ea[e * 3 + 1]);
    atomicAdd(&g_sea[d * 4 + 2], ea[e * 3 + 2]);
}

// ---------------- per-node gather: 4 nodes per warp, setup hoisted ------------
__global__ void k_gather(const float* __restrict__ eW, const float* __restrict__ eb,
                         const float* __restrict__ eps, int layer) {
    int warp = (blockIdx.x * blockDim.x + threadIdx.x) >> 5;
    int lane = threadIdx.x & 31;
    if (warp * 4 >= NN) return;
    int nb0 = warp * 4;
    int j = lane * 4;
    const float* W = eW + layer * EF * HH;
    float4 w0 = *(const float4*)(W + 0 * HH + j);
    float4 w1 = *(const float4*)(W + 1 * HH + j);
    float4 w2 = *(const float4*)(W + 2 * HH + j);
    float4 bv = *(const float4*)(eb + layer * HH + j);
    const float* hl = g_hcat + (size_t)layer * HH;
    float e1 = 1.f + eps[layer];

#pragma unroll
    for (int r = 0; r < 4; r++) {
        int node = nb0 + r;
        float4 hd = *(const float4*)(hl + (size_t)node * 512 + j);
        float4 S  = *(const float4*)(g_sea + node * 4);
        int start = g_rows[node] + g_boff[node >> 10];
        int deg = g_deg[node];
        const int* es = g_esrc + start;

        float dg = (float)deg;
        float ax = e1 * hd.x + dg * bv.x + S.x * w0.x + S.y * w1.x + S.z * w2.x;
        float ay = e1 * hd.y + dg * bv.y + S.x * w0.y + S.y * w1.y + S.z * w2.y;
        float az = e1 * hd.z + dg * bv.z + S.x * w0.z + S.y * w1.z + S.z * w2.z;
        float aw = e1 * hd.w + dg * bv.w + S.x * w0.w + S.y * w1.w + S.z * w2.w;
        float bx = 0.f, by = 0.f, bz = 0.f, bw = 0.f;

        int k = 0;
        for (; k + 4 <= deg; k += 4) {
            int s0 = es[k], s1 = es[k + 1], s2 = es[k + 2], s3 = es[k + 3];
            float4 h0 = *(const float4*)(hl + (size_t)s0 * 512 + j);
            float4 h1 = *(const float4*)(hl + (size_t)s1 * 512 + j);
            float4 h2 = *(const float4*)(hl + (size_t)s2 * 512 + j);
            float4 h3 = *(const float4*)(hl + (size_t)s3 * 512 + j);
            ax += h0.x; ay += h0.y; az += h0.z; aw += h0.w;
            bx += h1.x; by += h1.y; bz += h1.z; bw += h1.w;
            ax += h2.x; ay += h2.y; az += h2.z; aw += h2.w;
            bx += h3.x; by += h3.y; bz += h3.z; bw += h3.w;
        }
        for (; k < deg; k++) {
            int s0 = es[k];
            float4 h0 = *(const float4*)(hl + (size_t)s0 * 512 + j);
            ax += h0.x; ay += h0.y; az += h0.z; aw += h0.w;
        }
        uint2 o;
        o.x = pkh2(ax + bx, ay + by);
        o.y = pkh2(az + bz, aw + bw);
        *(uint2*)(g_aggh + (size_t)node * 64 + lane * 2) = o;
    }
}

// ---------------- fused GIN MLP: fp16 m16n8k16, BM=64, 256 thr, 2 CTA/SM ------
__global__ void __launch_bounds__(256, 2)
k_mlp(const uint32_t* __restrict__ Aagg, const uint32_t* __restrict__ W1p,
      const uint32_t* __restrict__ W2p,
      const float* __restrict__ b1v, const float* __restrict__ g1,
      const float* __restrict__ bt1, const float* __restrict__ rm1,
      const float* __restrict__ rv1,
      const float* __restrict__ b2v, const float* __restrict__ g2,
      const float* __restrict__ bt2, const float* __restrict__ rm2,
      const float* __restrict__ rv2,
      const float* __restrict__ hres,
      const float* __restrict__ lng, const float* __restrict__ lnb,
      float* __restrict__ out, uint32_t* __restrict__ outh) {
    constexpr int BM = 64;
    constexpr int NWG1 = 4, CH1 = 8;        // phase 1: K=128
    constexpr int NWG2 = 2;                 // phase 2: K=256, 8 stages of 2 chunks
    constexpr int ABYTES = BM * 48;         // 3072
    constexpr int B1BYTES = NWG1 * 32 * 80; // 10240
    constexpr int STG1 = ABYTES + B1BYTES;  // 13312 (x3 = 39936)
    constexpr int B2CH = NWG2 * 32 * 80;    // 5120 per chunk
    constexpr int B2STG = 2 * B2CH;         // 10240 per stage
    constexpr int ZS = 132;
    constexpr int W2RING = BM * ZS * 4;     // 33792; ring [33792, 64512)

    extern __shared__ char dsm[];
    __shared__ float red[BM * 4];
    uint32_t sb = sptr(dsm);

    int t = threadIdx.x;
    int lane = t & 31, wid = t >> 5;
    int lr = lane >> 2, lc = lane & 3;
    int n0 = blockIdx.x * BM;

    int mw = wid >> 2, nw = wid & 3;
    int wrow = mw * 32, wcol = nw * 64;

    float acc[2][8][4];
#pragma unroll
    for (int mt = 0; mt < 2; mt++)
#pragma unroll
        for (int nt = 0; nt < 8; nt++)
#pragma unroll
            for (int i = 0; i < 4; i++) acc[mt][nt][i] = 0.f;

    auto load_t1 = [&](int c, int st) {
        uint32_t ab = sb + st * STG1;
        uint32_t bb = ab + ABYTES;
        if (t < 128) {
            int r = t >> 1, c4 = t & 1;
            int n = n0 + r;
            const uint32_t* src = Aagg + (size_t)(n < NN ? n : 0) * 64 + c * 8 + c4 * 4;
            cp16(ab + r * 48 + c4 * 16, src, n < NN ? 16 : 0);
        }
#pragma unroll
        for (int i = 0; i < 2; i++) {
            int f = t + i * 256;
            cp16(bb + (f >> 2) * 80 + (f & 3) * 16, W1p + (size_t)c * 2048 + f * 4, 16);
        }
    };
    // stage s loads chunks 2s, 2s+1 of W2
    auto load_w2s = [&](int s, int jb) {
        uint32_t bb = sb + W2RING + jb * B2STG;
#pragma unroll
        for (int i = 0; i < 2; i++) {
            int f = t + i * 256;
            int h = f >> 8, f2 = f & 255;
            cp16(bb + h * B2CH + (f2 >> 2) * 80 + (f2 & 3) * 16,
                 W2p + (size_t)(s * 2 + h) * 1024 + f2 * 4, 16);
        }
    };

    load_t1(0, 0);
    cp_commit();
    load_t1(1, 1);
    cp_commit();
    for (int c = 0; c < CH1; c++) {
        int st = c % 3;
        if (c + 1 < CH1) cp_wait<1>(); else cp_wait<0>();
        __syncthreads();
        if (c + 2 < CH1) {
            load_t1(c + 2, (c + 2) % 3);
            cp_commit();
        }
        const uint32_t* As = (const uint32_t*)(dsm + st * STG1);
        const char*    Bb = dsm + st * STG1 + ABYTES;
        uint32_t a[2][4];
#pragma unroll
        for (int mt = 0; mt < 2; mt++) {
            int base = (wrow + mt * 16 + lr) * 12 + lc;
            a[mt][0] = As[base];
            a[mt][1] = As[base + 96];
            a[mt][2] = As[base + 4];
            a[mt][3] = As[base + 100];
        }
        const float4* bf = (const float4*)(Bb + (size_t)(nw * 32 + lane) * 80);
        uint32_t b[8][2];
#pragma unroll
        for (int g = 0; g < 4; g++) {
            float4 f4 = bf[g];
            b[2 * g + 0][0] = __float_as_uint(f4.x);
            b[2 * g + 0][1] = __float_as_uint(f4.y);
            b[2 * g + 1][0] = __float_as_uint(f4.z);
            b[2 * g + 1][1] = __float_as_uint(f4.w);
        }
#pragma unroll
        for (int mt = 0; mt < 2; mt++)
#pragma unroll
            for (int nt = 0; nt < 8; nt++)
                mma_f16(acc[mt][nt], a[mt], b[nt]);
    }
    __syncthreads();

    load_w2s(0, 0);
    cp_commit();
    load_w2s(1, 1);
    cp_commit();

    // ---- z = fp16(relu(bn1(acc + b1))) -> smem stash (packed half2) ----
    uint32_t* Zw = (uint32_t*)dsm;
    {
        float bsv[8][2], sc[8][2], sh[8][2];
#pragma unroll
        for (int nt = 0; nt < 8; nt++)
#pragma unroll
            for (int q = 0; q < 2; q++) {
                int col = wcol + nt * 8 + lc * 2 + q;
                bsv[nt][q] = b1v[col];
                float s = g1[col] * rsqrtf(rv1[col] + BN_EPS);
                sc[nt][q] = s;
                sh[nt][q] = bt1[col] - rm1[col] * s;
            }
#pragma unroll
        for (int mt = 0; mt < 2; mt++)
#pragma unroll
            for (int half = 0; half < 2; half++) {
                int row = wrow + mt * 16 + lr + half * 8;
#pragma unroll
                for (int nt = 0; nt < 8; nt++) {
                    float v0 = acc[mt][nt][half * 2 + 0] + bsv[nt][0];
                    v0 = fmaxf(v0 * sc[nt][0] + sh[nt][0], 0.f);
                    float v1 = acc[mt][nt][half * 2 + 1] + bsv[nt][1];
                    v1 = fmaxf(v1 * sc[nt][1] + sh[nt][1], 0.f);
                    Zw[row * ZS + wcol / 2 + nt * 4 + lc] = pkh2(v0, v1);
                }
            }
    }
    __syncthreads();

    // ---- phase 2: z @ W2, 8 stages of 2 chunks, warp tile 16x64, 8M x 2N ----
    int mw2 = wid >> 1, nw2 = wid & 1;
    int wrow2 = mw2 * 16, wcol2 = nw2 * 64;
    float acc2[8][4];
#pragma unroll
    for (int nt = 0; nt < 8; nt++)
#pragma unroll
        for (int i = 0; i < 4; i++) acc2[nt][i] = 0.f;

    for (int s2 = 0; s2 < 8; s2++) {
        int jb = s2 % 3;
        if (s2 + 1 < 8) cp_wait<1>(); else cp_wait<0>();
        __syncthreads();
        if (s2 + 2 < 8) {
            load_w2s(s2 + 2, (s2 + 2) % 3);
            cp_commit();
        }
#pragma unroll
        for (int h = 0; h < 2; h++) {
            int c2 = s2 * 2 + h;
            const char* Bb = dsm + W2RING + jb * B2STG + h * B2CH;
            uint32_t a[4];
            {
                int base = (wrow2 + lr) * ZS + c2 * 8 + lc;
                a[0] = Zw[base];
                a[1] = Zw[base + 8 * ZS];
                a[2] = Zw[base + 4];
                a[3] = Zw[base + 8 * ZS + 4];
            }
            const float4* bf = (const float4*)(Bb + (size_t)(nw2 * 32 + lane) * 80);
            uint32_t b[8][2];
#pragma unroll
            for (int g = 0; g < 4; g++) {
                float4 f4 = bf[g];
                b[2 * g + 0][0] = __float_as_uint(f4.x);
                b[2 * g + 0][1] = __float_as_uint(f4.y);
                b[2 * g + 1][0] = __float_as_uint(f4.z);
                b[2 * g + 1][1] = __float_as_uint(f4.w);
            }
#pragma unroll
            for (int nt = 0; nt < 8; nt++)
                mma_f16(acc2[nt], a, b[nt]);
        }
    }

    // ---- epilogue: bn2+relu + residual, LN, write hcat (fp32) + hcath (fp16) --
    float bsv2[8][2], sc2[8][2], sh2[8][2];
#pragma unroll
    for (int nt = 0; nt < 8; nt++)
#pragma unroll
        for (int q = 0; q < 2; q++) {
            int col = wcol2 + nt * 8 + lc * 2 + q;
            bsv2[nt][q] = b2v[col];
            float s = g2[col] * rsqrtf(rv2[col] + BN_EPS);
            sc2[nt][q] = s;
            sh2[nt][q] = bt2[col] - rm2[col] * s;
        }
#pragma unroll
    for (int half = 0; half < 2; half++) {
        int row = wrow2 + lr + half * 8;
        int n = n0 + row;
        float s = 0.f, sq = 0.f;
#pragma unroll
        for (int nt = 0; nt < 8; nt++)
#pragma unroll
            for (int q = 0; q < 2; q++) {
                int col = wcol2 + nt * 8 + lc * 2 + q;
                float v = acc2[nt][half * 2 + q] + bsv2[nt][q];
                v = fmaxf(v * sc2[nt][q] + sh2[nt][q], 0.f);
                if (n < NN) v += hres[(size_t)n * 512 + col];
                acc2[nt][half * 2 + q] = v;
                s += v;
                sq += v * v;
            }
        s  += __shfl_xor_sync(0xffffffffu, s, 1);
        sq += __shfl_xor_sync(0xffffffffu, sq, 1);
        s  += __shfl_xor_sync(0xffffffffu, s, 2);
        sq += __shfl_xor_sync(0xffffffffu, sq, 2);
        if (lc == 0) {
            red[(row * 2 + nw2) * 2 + 0] = s;
            red[(row * 2 + nw2) * 2 + 1] = sq;
        }
    }
    __syncthreads();
#pragma unroll
    for (int half = 0; half < 2; half++) {
        int row = wrow2 + lr + half * 8;
        int n = n0 + row;
        if (n >= NN) continue;
        float s  = red[(row * 2 + 0) * 2 + 0] + red[(row * 2 + 1) * 2 + 0];
        float sq = red[(row * 2 + 0) * 2 + 1] + red[(row * 2 + 1) * 2 + 1];
        float mu = s * (1.f / 128.f);
        float var = sq * (1.f / 128.f) - mu * mu;
        float inv = rsqrtf(var + LN_EPS);
#pragma unroll
        for (int nt = 0; nt < 8; nt++) {
            int col0 = wcol2 + nt * 8 + lc * 2;
            float o0 = (acc2[nt][half * 2 + 0] - mu) * inv * lng[col0] + lnb[col0];
            float o1 = (acc2[nt][half * 2 + 1] - mu) * inv * lng[col0 + 1] + lnb[col0 + 1];
            *(float2*)(out + (size_t)n * 512 + col0) = make_float2(o0, o1);
            outh[(size_t)n * 256 + col0 / 2] = pkh2(o0, o1);
        }
    }
}

// ---------------- fused output head: fp16, A from packed hcath ----------------
__global__ void __launch_bounds__(256, 2)
k_gemm_out(const uint32_t* __restrict__ Ah, const uint32_t* __restrict__ W1p,
           const uint32_t* __restrict__ W2p,
           const float* __restrict__ b1, const float* __restrict__ b2,
           float* __restrict__ out) {
    constexpr int NWG = 2, BM = 128;
    constexpr int CH = 32;                  // K=512, chunks of 16
    constexpr int ABYTES = BM * 48;         // 6144
    constexpr int BBYTES = NWG * 32 * 80;   // 5120
    constexpr int STG = ABYTES + BBYTES;    // 11264 (x3 = 33792)
    constexpr int B2CH = 5120, B2STG = 10240;
    constexpr int ZS = 68;
    constexpr int B2OFF = BM * ZS * 4;      // 34816; ring [34816, 65536)

    extern __shared__ char dsm[];
    uint32_t sb = sptr(dsm);

    int t = threadIdx.x;
    int lane = t & 31, wid = t >> 5;
    int mw = wid >> 1, nw = wid & 1;
    int wrow = mw * 32, wcol = nw * 64;
    int lr = lane >> 2, lc = lane & 3;
    int n0 = blockIdx.x * BM;

    float acc[2][8][4];
#pragma unroll
    for (int mt = 0; mt < 2; mt++)
#pragma unroll
        for (int nt = 0; nt < 8; nt++)
#pragma unroll
            for (int i = 0; i < 4; i++) acc[mt][nt][i] = 0.f;

    auto load_tiles = [&](int c, int st) {
        uint32_t ab = sb + st * STG;
        uint32_t bb = ab + ABYTES;
        {   // A: 128 rows x 8 words, 1 cp16 per thread
            int r = t >> 1, c4 = t & 1;
            int n = n0 + r;
            const uint32_t* src = Ah + (size_t)(n < NN ? n : 0) * 256 + c * 8 + c4 * 4;
            cp16(ab + r * 48 + c4 * 16, src, n < NN ? 16 : 0);
        }
        cp16(bb + (t >> 2) * 80 + (t & 3) * 16, W1p + (size_t)c * 1024 + t * 4, 16);
    };
    auto load_w2s = [&](int s, int jb) {
        uint32_t bb = sb + B2OFF + jb * B2STG;
#pragma unroll
        for (int i = 0; i < 2; i++) {
            int f = t + i * 256;
            int h = f >> 8, f2 = f & 255;
            cp16(bb + h * B2CH + (f2 >> 2) * 80 + (f2 & 3) * 16,
                 W2p + (size_t)(s * 2 + h) * 1024 + f2 * 4, 16);
        }
    };

    load_tiles(0, 0);
    cp_commit();
    load_tiles(1, 1);
    cp_commit();
    for (int c = 0; c < CH; c++) {
        int st = c % 3;
        if (c + 1 < CH) cp_wait<1>(); else cp_wait<0>();
        __syncthreads();
        if (c + 2 < CH) {
            load_tiles(c + 2, (c + 2) % 3);
            cp_commit();
        }
        const uint32_t* As = (const uint32_t*)(dsm + st * STG);
        const char*    Bb = dsm + st * STG + ABYTES;
        uint32_t a[2][4];
#pragma unroll
        for (int mt = 0; mt < 2; mt++) {
            int base = (wrow + mt * 16 + lr) * 12 + lc;
            a[mt][0] = As[base];
            a[mt][1] = As[base + 96];
            a[mt][2] = As[base + 4];
            a[mt][3] = As[base + 100];
        }
        const float4* bf = (const float4*)(Bb + (size_t)(nw * 32 + lane) * 80);
        uint32_t b[8][2];
#pragma unroll
        for (int g = 0; g < 4; g++) {
            float4 f4 = bf[g];
            b[2 * g + 0][0] = __float_as_uint(f4.x);
            b[2 * g + 0][1] = __float_as_uint(f4.y);
            b[2 * g + 1][0] = __float_as_uint(f4.z);
            b[2 * g + 1][1] = __float_as_uint(f4.w);
        }
#pragma unroll
        for (int mt = 0; mt < 2; mt++)
#pragma unroll
            for (int nt = 0; nt < 8; nt++)
                mma_f16(acc[mt][nt], a[mt], b[nt]);
    }
    __syncthreads();

    load_w2s(0, 0);
    cp_commit();
    load_w2s(1, 1);
    cp_commit();

    uint32_t* Zw = (uint32_t*)dsm;
    {
        float bsv[8][2];
#pragma unroll
        for (int nt = 0; nt < 8; nt++)
#pragma unroll
            for (int q = 0; q < 2; q++)
                bsv[nt][q] = b1[wcol + nt * 8 + lc * 2 + q];
#pragma unroll
        for (int mt = 0; mt < 2; mt++)
#pragma unroll
            for (int half = 0; half < 2; half++) {
                int row = wrow + mt * 16 + lr + half * 8;
#pragma unroll
                for (int nt = 0; nt < 8; nt++) {
                    float v0 = fmaxf(acc[mt][nt][half * 2 + 0] + bsv[nt][0], 0.f);
                    float v1 = fmaxf(acc[mt][nt][half * 2 + 1] + bsv[nt][1], 0.f);
                    Zw[row * ZS + wcol / 2 + nt * 4 + lc] = pkh2(v0, v1);
                }
            }
    }
    __syncthreads();

#pragma unroll
    for (int mt = 0; mt < 2; mt++)
#pragma unroll
        for (int nt = 0; nt < 8; nt++)
#pragma unroll
            for (int i = 0; i < 4; i++) acc[mt][nt][i] = 0.f;

    // phase 2: 4 stages of 2 chunks (K=128)
    for (int s2 = 0; s2 < 4; s2++) {
        int jb = s2 % 3;
        if (s2 + 1 < 4) cp_wait<1>(); else cp_wait<0>();
        __syncthreads();
        if (s2 + 2 < 4) {
            load_w2s(s2 + 2, (s2 + 2) % 3);
            cp_commit();
        }
#pragma unroll
        for (int h = 0; h < 2; h++) {
            int c2 = s2 * 2 + h;
            const char* Bb = dsm + B2OFF + jb * B2STG + h * B2CH;
            uint32_t a[2][4];
#pragma unroll
            for (int mt = 0; mt < 2; mt++) {
                int base = (wrow + mt * 16 + lr) * ZS + c2 * 8 + lc;
                a[mt][0] = Zw[base];
                a[mt][1] = Zw[base + 8 * ZS];
                a[mt][2] = Zw[base + 4];
                a[mt][3] = Zw[base + 8 * ZS + 4];
            }
            const float4* bf = (const float4*)(Bb + (size_t)(nw * 32 + lane) * 80);
            uint32_t b[8][2];
#pragma unroll
            for (int g = 0; g < 4; g++) {
                float4 f4 = bf[g];
                b[2 * g + 0][0] = __float_as_uint(f4.x);
                b[2 * g + 0][1] = __float_as_uint(f4.y);
                b[2 * g + 1][0] = __float_as_uint(f4.z);
                b[2 * g + 1][1] = __float_as_uint(f4.w);
            }
#pragma unroll
            for (int mt = 0; mt < 2; mt++)
#pragma unroll
                for (int nt = 0; nt < 8; nt++)
                    mma_f16(acc[mt][nt], a[mt], b[nt]);
        }
    }

    float bsv2[8][2];
#pragma unroll
    for (int nt = 0; nt < 8; nt++)
#pragma unroll
        for (int q = 0; q < 2; q++)
            bsv2[nt][q] = b2[wcol + nt * 8 + lc * 2 + q];
#pragma unroll
    for (int mt = 0; mt < 2; mt++)
#pragma unroll
        for (int half = 0; half < 2; half++) {
            int row = wrow + mt * 16 + lr + half * 8;
            int n = n0 + row;
            if (n >= NN) continue;
#pragma unroll
            for (int nt = 0; nt < 8; nt++)
#pragma unroll
                for (int q = 0; q < 2; q++) {
                    int col = wcol + nt * 8 + lc * 2 + q;
                    out[(size_t)n * 128 + col] =
                        acc[mt][nt][half * 2 + q] + bsv2[nt][q];
                }
        }
}

// ---------------- pool ---------------------------------------------------------
__global__ void k_pool(const int* __restrict__ batch, const float* __restrict__ emb) {
    int c = blockIdx.x;
    int j = threadIdx.x;
    int n0 = c * 32;
    __shared__ int sb[32];
    if (j < 32) sb[j] = (n0 + j < NN) ? batch[n0 + j] : -1;
    __syncthreads();
    float acc = 0.f;
    int bcur = sb[0];
    for (int m = 0; m < 32; m++) {
        int b = sb[m];
        if (b < 0) break;
        if (b != bcur) {
            atomicAdd(&g_gsum[bcur * HH + j], acc);
            acc = 0.f;
            bcur = b;
        }
        acc += emb[(size_t)(n0 + m) * HH + j];
    }
    if (bcur >= 0) atomicAdd(&g_gsum[bcur * HH + j], acc);
    if (j == 0) {
        float cn = 0.f;
        int bc = sb[0];
        for (int m = 0; m < 32; m++) {
            int b = sb[m];
            if (b < 0) break;
            if (b != bc) { atomicAdd(&g_cnt[bc], cn); cn = 0.f; bc = b; }
            cn += 1.f;
        }
        if (bc >= 0) atomicAdd(&g_cnt[bc], cn);
    }
}

__global__ void k_finish(float* __restrict__ out_graph) {
    int i = blockIdx.x * blockDim.x + threadIdx.x;
    if (i >= BB * HH) return;
    out_graph[i] = g_gsum[i] / fmaxf(g_cnt[i >> 7], 1.f);
}

// ---------------- launcher ------------------------------------------------------
extern "C" void kernel_launch(void* const* d_in, const int* in_sizes, int n_in,
                              void* d_out, int out_size) {
    const float* x      = (const float*)d_in[0];
    const int*   ei     = (const int*)  d_in[1];
    const float* ea     = (const float*)d_in[2];
    const int*   batch  = (const int*)  d_in[3];
    const float* in_W   = (const float*)d_in[4];
    const float* in_b   = (const float*)d_in[5];
    const float* edge_W = (const float*)d_in[6];
    const float* edge_b = (const float*)d_in[7];
    const float* mlp_W1 = (const float*)d_in[8];
    const float* mlp_b1 = (const float*)d_in[9];
    const float* bn1_g  = (const float*)d_in[10];
    const float* bn1_b  = (const float*)d_in[11];
    const float* bn1_rm = (const float*)d_in[12];
    const float* bn1_rv = (const float*)d_in[13];
    const float* mlp_W2 = (const float*)d_in[14];
    const float* mlp_b2 = (const float*)d_in[15];
    const float* bn2_g  = (const float*)d_in[16];
    const float* bn2_b  = (const float*)d_in[17];
    const float* bn2_rm = (const float*)d_in[18];
    const float* bn2_rv = (const float*)d_in[19];
    const float* eps    = (const float*)d_in[20];
    const float* ln_g   = (const float*)d_in[21];
    const float* ln_b   = (const float*)d_in[22];
    const float* out_W1 = (const float*)d_in[23];
    const float* out_b1 = (const float*)d_in[24];
    const float* out_W2 = (const float*)d_in[25];
    const float* out_b2 = (const float*)d_in[26];

    float* node_emb  = (float*)d_out;
    float* graph_emb = (float*)d_out + (size_t)NN * HH;

    float*    g_hcat_p;  cudaGetSymbolAddress((void**)&g_hcat_p,  g_hcat);
    uint32_t* g_hcath_p; cudaGetSymbolAddress((void**)&g_hcath_p, g_hcath);
    uint32_t* g_aggh_p;  cudaGetSymbolAddress((void**)&g_aggh_p,  g_aggh);
    uint32_t* g_wtf_p;   cudaGetSymbolAddress((void**)&g_wtf_p,   g_wtf);

    const int SMMLP = 64512;   // z(33792) + W2 ring(30720); covers 39936 p1 ring
    const int SMOUT = 65536;   // z(34816) + W2 ring(30720); covers 33792 p1 ring
    cudaFuncSetAttribute(k_mlp,
                         cudaFuncAttributeMaxDynamicSharedMemorySize, SMMLP);
    cudaFuncSetAttribute(k_gemm_out,
                         cudaFuncAttributeMaxDynamicSharedMemorySize, SMOUT);

    const int NT = 256;
    k_prep<<<(WTOT + NT - 1) / NT, NT>>>(mlp_W1, mlp_W2, out_W1, out_W2);
    k_input<<<(NN * 64 + NT - 1) / NT, NT>>>(x, in_W, in_b);

    // CSR build
    k_count<<<(EE + NT - 1) / NT, NT>>>(ei);
    k_scan1<<<(NN + 1023) / 1024, 256>>>();
    k_scan2<<<1, 128>>>((NN + 1023) / 1024);
    k_place<<<(EE + NT - 1) / NT, NT>>>(ei, ea);

    const int ggrid  = (NN / 4 * 32 + NT - 1) / NT;   // 4 nodes per warp
    const int grid64  = (NN + 63) / 64;
    const int grid128 = (NN + 127) / 128;
    for (int l = 0; l < LL; l++) {
        k_gather<<<ggrid, NT>>>(edge_W, edge_b, eps, l);
        k_mlp<<<grid64, 256, SMMLP>>>(
            g_aggh_p,
            g_wtf_p + W1OFF + (size_t)l * 16384,
            g_wtf_p + W2OFF + (size_t)l * 16384,
            mlp_b1 + l * 256, bn1_g + l * 256, bn1_b + l * 256,
            bn1_rm + l * 256, bn1_rv + l * 256,
            mlp_b2 + l * 128, bn2_g + l * 128, bn2_b + l * 128,
            bn2_rm + l * 128, bn2_rv + l * 128,
            g_hcat_p + l * HH, ln_g + l * 128, ln_b + l * 128,
            g_hcat_p + (l + 1) * HH, g_hcath_p + (l + 1) * 64);
    }
    k_gemm_out<<<grid128, 256, SMOUT>>>(
        g_hcath_p, g_wtf_p + O1OFF, g_wtf_p + O2OFF, out_b1, out_b2, node_emb);

    k_pool<<<(NN + 31) / 32, 128>>>(batch, node_emb);
    k_finish<<<(BB * HH + NT - 1) / NT, NT>>>(graph_emb);
}